// round 1
// baseline (speedup 1.0000x reference)
#include <cuda_runtime.h>
#include <cuda_bf16.h>

#define N_ 16
#define C_ 256
#define T_ 300
#define V_ 25
#define K_ 3
#define TK_ 9
#define O_ (K_ * C_)          // 768
#define J_ (T_ * V_)          // 7500
#define BN_EPS 1e-5f

// scratch (static device buffers; no runtime allocation)
__device__ float g_buf[N_ * C_ * J_];       // 30,720,000 floats = 122.88 MB
__device__ float wt_buf[TK_ * C_ * C_];     // Wt[dt][ci][co]

// ---------------------------------------------------------------------------
// Kernel 0: transpose temporal conv weights (co,ci,dt,1) -> (dt,ci,co)
// ---------------------------------------------------------------------------
__global__ void wt_kernel(const float* __restrict__ tw) {
    int i = blockIdx.x * 256 + threadIdx.x;
    if (i < TK_ * C_ * C_) {
        int dt = i / (C_ * C_);
        int r  = i - dt * C_ * C_;
        int ci = r / C_;
        int co = r - ci * C_;
        wt_buf[i] = tw[(co * C_ + ci) * TK_ + dt];
    }
}

// ---------------------------------------------------------------------------
// Kernel 1: fused 1x1-conv GEMM + graph contraction (A*M) + BN1 + ReLU -> g_buf
// one block per (t, n); 256 threads; thread tid owns output channel c = tid
// ---------------------------------------------------------------------------
__global__ void __launch_bounds__(256) sgc_kernel(
    const float* __restrict__ x, const float* __restrict__ A,
    const float* __restrict__ Mm, const float* __restrict__ W,
    const float* __restrict__ bias,
    const float* __restrict__ bg, const float* __restrict__ bb,
    const float* __restrict__ bm, const float* __restrict__ bv)
{
    extern __shared__ float sm[];
    float* xs  = sm;                       // C_*V_ = 6400
    float* AMs = sm + C_ * V_;             // 3*25*25 = 1875
    float* Wch = sm + C_ * V_ + K_ * V_ * V_;  // 32 * 769 (padded)

    const int t = blockIdx.x;
    const int n = blockIdx.y;
    const int tid = threadIdx.x;

    // load x[n, :, t, :] slice (256 x 25)
    const float* xbase = x + (n * C_ * T_ + t) * V_;
    for (int i = tid; i < C_ * V_; i += 256) {
        int ci = i / V_;
        int v  = i - ci * V_;
        xs[i] = xbase[ci * (T_ * V_) + v];
    }
    // A * M elementwise
    for (int i = tid; i < K_ * V_ * V_; i += 256)
        AMs[i] = A[i] * Mm[i];
    __syncthreads();

    float acc[K_][V_];
    #pragma unroll
    for (int k = 0; k < K_; ++k)
        #pragma unroll
        for (int v = 0; v < V_; ++v) acc[k][v] = 0.f;

    for (int cic = 0; cic < C_; cic += 32) {
        // cooperative load of W[:, cic:cic+32], transposed into smem
        for (int i = tid; i < 32 * O_; i += 256) {
            int o  = i >> 5;
            int cc = i & 31;
            Wch[cc * 769 + o] = W[o * C_ + cic + cc];
        }
        __syncthreads();

        #pragma unroll 2
        for (int cc = 0; cc < 32; ++cc) {
            const float* xr = xs + (cic + cc) * V_;
            float w0 = Wch[cc * 769 + tid];
            float w1 = Wch[cc * 769 + C_ + tid];
            float w2 = Wch[cc * 769 + 2 * C_ + tid];
            #pragma unroll
            for (int v = 0; v < V_; ++v) {
                float xv = xr[v];
                acc[0][v] = fmaf(w0, xv, acc[0][v]);
                acc[1][v] = fmaf(w1, xv, acc[1][v]);
                acc[2][v] = fmaf(w2, xv, acc[2][v]);
            }
        }
        __syncthreads();
    }

    // bias + contraction with A*M: sgc[c,w] = sum_{k,v} (y[k,c,v]+b) * AM[k,v,w]
    float b0 = bias[tid], b1 = bias[C_ + tid], b2 = bias[2 * C_ + tid];
    float outv[V_];
    #pragma unroll
    for (int w = 0; w < V_; ++w) outv[w] = 0.f;

    #pragma unroll
    for (int k = 0; k < K_; ++k) {
        float bk = (k == 0) ? b0 : ((k == 1) ? b1 : b2);
        #pragma unroll
        for (int v = 0; v < V_; ++v) {
            float yv = acc[k][v] + bk;
            const float* am = AMs + (k * V_ + v) * V_;
            #pragma unroll
            for (int w = 0; w < V_; ++w)
                outv[w] = fmaf(yv, am[w], outv[w]);
        }
    }

    // BN1 + ReLU, store to g_buf
    float sc = bg[tid] * rsqrtf(bv[tid] + BN_EPS);
    float sh = bb[tid] - bm[tid] * sc;
    float* gout = g_buf + ((n * C_ + tid) * T_ + t) * V_;
    #pragma unroll
    for (int w = 0; w < V_; ++w) {
        float r = fmaf(outv[w], sc, sh);
        gout[w] = r > 0.f ? r : 0.f;
    }
}

// ---------------------------------------------------------------------------
// Kernel 2: temporal conv (implicit GEMM, K = 256*9) + BN2 + ReLU + residual
// tile: 128 co x 64 j-cols; 256 threads; each thread 8x4 accumulators
// ---------------------------------------------------------------------------
#define TILE_CO 128
#define TILE_J  64
#define CK      32

__global__ void __launch_bounds__(256) tconv_kernel(
    const float* __restrict__ x, const float* __restrict__ tcb,
    const float* __restrict__ g2, const float* __restrict__ b2,
    const float* __restrict__ m2, const float* __restrict__ v2,
    float* __restrict__ out)
{
    __shared__ float Ws[CK][TILE_CO];
    __shared__ float Gs[CK][TILE_J];

    const int tid = threadIdx.x;
    const int j0  = blockIdx.x * TILE_J;
    const int co0 = blockIdx.y * TILE_CO;
    const int n   = blockIdx.z;
    const int tx  = tid & 15;   // 16 col-groups of 4
    const int ty  = tid >> 4;   // 16 row-groups of 8

    float acc[8][4];
    #pragma unroll
    for (int i = 0; i < 8; ++i)
        #pragma unroll
        for (int j = 0; j < 4; ++j) acc[i][j] = 0.f;

    const float* gn = g_buf + n * (C_ * J_);

    for (int dt = 0; dt < TK_; ++dt) {
        const int s = (dt - (TK_ - 1) / 2) * V_;
        const float* Wdt = wt_buf + dt * (C_ * C_) + co0;

        for (int cic = 0; cic < C_; cic += CK) {
            // load weight tile (coalesced: rows of 128 floats)
            #pragma unroll
            for (int i = tid; i < CK * TILE_CO; i += 256) {
                int cc  = i >> 7;
                int col = i & (TILE_CO - 1);
                Ws[cc][col] = Wdt[(cic + cc) * C_ + col];
            }
            // load shifted g tile with zero-padding outside [0, J_)
            #pragma unroll
            for (int i = tid; i < CK * TILE_J; i += 256) {
                int cc = i >> 6;
                int jc = i & (TILE_J - 1);
                int jj = j0 + jc + s;
                float val = 0.f;
                if (jj >= 0 && jj < J_)
                    val = gn[(cic + cc) * J_ + jj];
                Gs[cc][jc] = val;
            }
            __syncthreads();

            #pragma unroll
            for (int cc = 0; cc < CK; ++cc) {
                float a[8], b[4];
                #pragma unroll
                for (int i = 0; i < 8; ++i) a[i] = Ws[cc][ty * 8 + i];
                #pragma unroll
                for (int j = 0; j < 4; ++j) b[j] = Gs[cc][tx * 4 + j];
                #pragma unroll
                for (int i = 0; i < 8; ++i)
                    #pragma unroll
                    for (int j = 0; j < 4; ++j)
                        acc[i][j] = fmaf(a[i], b[j], acc[i][j]);
            }
            __syncthreads();
        }
    }

    // epilogue: fold tconv bias into BN2 shift, ReLU, residual
    #pragma unroll
    for (int i = 0; i < 8; ++i) {
        int co = co0 + ty * 8 + i;
        float scl = g2[co] * rsqrtf(v2[co] + BN_EPS);
        float shf = b2[co] - m2[co] * scl + tcb[co] * scl;
        const float* xr = x + (n * C_ + co) * J_;
        float* orow = out + (n * C_ + co) * J_;
        #pragma unroll
        for (int j = 0; j < 4; ++j) {
            int jj = j0 + tx * 4 + j;
            if (jj < J_) {
                float r = fmaf(acc[i][j], scl, shf);
                r = r > 0.f ? r : 0.f;
                orow[jj] = r + xr[jj];
            }
        }
    }
}

// ---------------------------------------------------------------------------
extern "C" void kernel_launch(void* const* d_in, const int* in_sizes, int n_in,
                              void* d_out, int out_size)
{
    const float* x   = (const float*)d_in[0];
    const float* A   = (const float*)d_in[1];
    // d_in[2] = att_A (unused by this block)
    const float* Mm  = (const float*)d_in[3];
    const float* W   = (const float*)d_in[4];
    const float* cb  = (const float*)d_in[5];
    const float* g1  = (const float*)d_in[6];
    const float* b1  = (const float*)d_in[7];
    const float* m1  = (const float*)d_in[8];
    const float* v1  = (const float*)d_in[9];
    const float* tw  = (const float*)d_in[10];
    const float* tcb = (const float*)d_in[11];
    const float* g2  = (const float*)d_in[12];
    const float* b2  = (const float*)d_in[13];
    const float* m2  = (const float*)d_in[14];
    const float* v2  = (const float*)d_in[15];
    float* out = (float*)d_out;

    // opt-in to >48KB dynamic smem for sgc_kernel (idempotent)
    const int smem1 = (C_ * V_ + K_ * V_ * V_ + 32 * 769) * (int)sizeof(float);
    cudaFuncSetAttribute(sgc_kernel, cudaFuncAttributeMaxDynamicSharedMemorySize, smem1);

    // K0: weight transform
    wt_kernel<<<(TK_ * C_ * C_ + 255) / 256, 256>>>(tw);

    // K1: S_GC + BN1 + ReLU
    dim3 grid1(T_, N_);
    sgc_kernel<<<grid1, 256, smem1>>>(x, A, Mm, W, cb, g1, b1, m1, v1);

    // K2: temporal conv + BN2 + ReLU + residual
    dim3 grid2((J_ + TILE_J - 1) / TILE_J, C_ / TILE_CO, N_);
    tconv_kernel<<<grid2, 256>>>(x, tcb, g2, b2, m2, v2, out);
}

// round 3
// speedup vs baseline: 1.7833x; 1.7833x over previous
#include <cuda_runtime.h>
#include <cuda_fp16.h>
#include <cstdint>

#define N_ 16
#define C_ 256
#define T_ 300
#define V_ 25
#define K_ 3
#define TK_ 9
#define O_ (K_ * C_)          // 768
#define J_ (T_ * V_)          // 7500
#define BN_EPS 1e-5f

// scratch (static device buffers; no runtime allocation)
__device__ __align__(256) __half gt_buf[N_ * J_ * C_];    // g transposed [n][j][ci], fp16
__device__ __align__(256) __half wt2_buf[TK_ * C_ * C_];  // Wt2[dt][co][ci], fp16

// ---------------------------------------------------------------------------
// PTX helpers (baseline ISA only: ldmatrix / mma.sync / cp.async)
// ---------------------------------------------------------------------------
__device__ __forceinline__ uint32_t smem_u32(const void* p) {
    uint32_t a;
    asm("{ .reg .u64 t; cvta.to.shared.u64 t, %1; cvt.u32.u64 %0, t; }" : "=r"(a) : "l"(p));
    return a;
}

__device__ __forceinline__ void ldsm4(uint32_t* r, uint32_t addr) {
    asm volatile("ldmatrix.sync.aligned.m8n8.x4.shared.b16 {%0,%1,%2,%3}, [%4];"
                 : "=r"(r[0]), "=r"(r[1]), "=r"(r[2]), "=r"(r[3]) : "r"(addr));
}

__device__ __forceinline__ void mma16816(float* c, const uint32_t* a,
                                         uint32_t b0, uint32_t b1) {
    asm volatile(
        "mma.sync.aligned.m16n8k16.row.col.f32.f16.f16.f32 "
        "{%0,%1,%2,%3}, {%4,%5,%6,%7}, {%8,%9}, {%0,%1,%2,%3};"
        : "+f"(c[0]), "+f"(c[1]), "+f"(c[2]), "+f"(c[3])
        : "r"(a[0]), "r"(a[1]), "r"(a[2]), "r"(a[3]), "r"(b0), "r"(b1));
}

__device__ __forceinline__ void cpa16(uint32_t dst, const void* src, int srcsize) {
    asm volatile("cp.async.cg.shared.global [%0], [%1], 16, %2;"
                 :: "r"(dst), "l"(src), "r"(srcsize));
}
__device__ __forceinline__ void cpa_commit() {
    asm volatile("cp.async.commit_group;" ::: "memory");
}
template <int NN>
__device__ __forceinline__ void cpa_wait() {
    asm volatile("cp.async.wait_group %0;" :: "n"(NN) : "memory");
}

// ---------------------------------------------------------------------------
// Kernel 0: weight transform (co,ci,dt) -> Wt2[dt][co][ci], fp16
// ---------------------------------------------------------------------------
__global__ void wt2_kernel(const float* __restrict__ tw) {
    int i = blockIdx.x * 256 + threadIdx.x;
    if (i < TK_ * C_ * C_) {
        int dt = i / (C_ * C_);
        int r  = i - dt * C_ * C_;
        int co = r >> 8;
        int ci = r & 255;
        wt2_buf[i] = __float2half_rn(tw[(co * C_ + ci) * TK_ + dt]);
    }
}

// ---------------------------------------------------------------------------
// Kernel 1: fused 1x1-conv GEMM + graph contraction (A*M) + BN1 + ReLU
// writes TRANSPOSED g_t[n][j][ci] in fp16 for the MMA kernel's B operand.
// ---------------------------------------------------------------------------
__global__ void __launch_bounds__(256) sgc_kernel(
    const float* __restrict__ x, const float* __restrict__ A,
    const float* __restrict__ Mm, const float* __restrict__ W,
    const float* __restrict__ bias,
    const float* __restrict__ bg, const float* __restrict__ bb,
    const float* __restrict__ bm, const float* __restrict__ bv)
{
    extern __shared__ float sm1[];
    float* xs  = sm1;                          // C_*V_ = 6400
    float* AMs = sm1 + C_ * V_;                // 3*25*25 = 1875
    float* Wch = sm1 + C_ * V_ + K_ * V_ * V_; // 32 * 769 (padded)

    const int t = blockIdx.x;
    const int n = blockIdx.y;
    const int tid = threadIdx.x;

    const float* xbase = x + (n * C_ * T_ + t) * V_;
    for (int i = tid; i < C_ * V_; i += 256) {
        int ci = i / V_;
        int v  = i - ci * V_;
        xs[i] = xbase[ci * (T_ * V_) + v];
    }
    for (int i = tid; i < K_ * V_ * V_; i += 256)
        AMs[i] = A[i] * Mm[i];
    __syncthreads();

    float acc[K_][V_];
    #pragma unroll
    for (int k = 0; k < K_; ++k)
        #pragma unroll
        for (int v = 0; v < V_; ++v) acc[k][v] = 0.f;

    for (int cic = 0; cic < C_; cic += 32) {
        for (int i = tid; i < 32 * O_; i += 256) {
            int o  = i >> 5;
            int cc = i & 31;
            Wch[cc * 769 + o] = W[o * C_ + cic + cc];
        }
        __syncthreads();

        #pragma unroll 2
        for (int cc = 0; cc < 32; ++cc) {
            const float* xr = xs + (cic + cc) * V_;
            float w0 = Wch[cc * 769 + tid];
            float w1 = Wch[cc * 769 + C_ + tid];
            float w2 = Wch[cc * 769 + 2 * C_ + tid];
            #pragma unroll
            for (int v = 0; v < V_; ++v) {
                float xv = xr[v];
                acc[0][v] = fmaf(w0, xv, acc[0][v]);
                acc[1][v] = fmaf(w1, xv, acc[1][v]);
                acc[2][v] = fmaf(w2, xv, acc[2][v]);
            }
        }
        __syncthreads();
    }

    float b0 = bias[tid], b1 = bias[C_ + tid], b2 = bias[2 * C_ + tid];
    float outv[V_];
    #pragma unroll
    for (int w = 0; w < V_; ++w) outv[w] = 0.f;

    #pragma unroll
    for (int k = 0; k < K_; ++k) {
        float bk = (k == 0) ? b0 : ((k == 1) ? b1 : b2);
        #pragma unroll
        for (int v = 0; v < V_; ++v) {
            float yv = acc[k][v] + bk;
            const float* am = AMs + (k * V_ + v) * V_;
            #pragma unroll
            for (int w = 0; w < V_; ++w)
                outv[w] = fmaf(yv, am[w], outv[w]);
        }
    }

    float sc = bg[tid] * rsqrtf(bv[tid] + BN_EPS);
    float sh = bb[tid] - bm[tid] * sc;
    // transposed store: g_t[n][t*25+w][tid]
    __half* gout = gt_buf + (size_t)(n * J_ + t * V_) * C_ + tid;
    #pragma unroll
    for (int w = 0; w < V_; ++w) {
        float r = fmaf(outv[w], sc, sh);
        r = r > 0.f ? r : 0.f;
        gout[(size_t)w * C_] = __float2half_rn(r);
    }
}

// ---------------------------------------------------------------------------
// Kernel 2: temporal conv as fp16 mma.sync implicit GEMM + BN2 + ReLU + resid
// CTA tile: 128 co x 128 j; 8 warps (4 m-groups x 2 n-groups), warp 32x64
// K loop: 72 stages of k=32 (9 dt x 8 ci-chunks), double-buffered cp.async
// ---------------------------------------------------------------------------
#define ROW_B 80                 // smem row stride bytes (32 halfs + 8 pad)
#define A_BYTES (128 * ROW_B)    // 10240
#define STAGE (2 * A_BYTES)      // 20480
#define NUM_IT (TK_ * 8)         // 72

__global__ void __launch_bounds__(256, 2) tconv_mma_kernel(
    const float* __restrict__ x, const float* __restrict__ tcb,
    const float* __restrict__ g2, const float* __restrict__ b2,
    const float* __restrict__ m2, const float* __restrict__ v2,
    float* __restrict__ out)
{
    __shared__ __align__(16) char smraw[2 * STAGE];
    const uint32_t sb = smem_u32(smraw);

    const int tid  = threadIdx.x;
    const int wid  = tid >> 5;
    const int lane = tid & 31;
    const int j0   = blockIdx.x * 128;
    const int co0  = blockIdx.y * 128;
    const int n    = blockIdx.z;

    const int wm = wid & 3;          // 4 m-groups of 32 co
    const int wn = wid >> 2;         // 2 n-groups of 64 j
    const int cw = wm * 32;
    const int jw = wn * 64;

    const __half* gtn = gt_buf + (size_t)n * (J_ * C_);

    float acc[2][8][4];
    #pragma unroll
    for (int mi = 0; mi < 2; ++mi)
        #pragma unroll
        for (int nf = 0; nf < 8; ++nf)
            #pragma unroll
            for (int q = 0; q < 4; ++q) acc[mi][nf][q] = 0.f;

    // precomputed ldmatrix offsets (relative to stage base)
    uint32_t offA[2], offB[4];
    {
        const int rA = (lane & 15);
        const int kA = (lane >> 4) << 4;   // 0 or 16 bytes
        #pragma unroll
        for (int mi = 0; mi < 2; ++mi)
            offA[mi] = (uint32_t)((cw + mi * 16 + rA) * ROW_B + kA);
        const int rB = (lane & 7) + (((lane >> 4) & 1) << 3);
        const int kB = ((lane >> 3) & 1) << 4;
        #pragma unroll
        for (int nb = 0; nb < 4; ++nb)
            offB[nb] = (uint32_t)(A_BYTES + (jw + nb * 16 + rB) * ROW_B + kB);
    }

    // ---- stage loader (2 A-chunks + 2 B-chunks per thread) ----
    auto load_stage = [&](int it) {
        const int dt  = it >> 3;
        const int cic = (it & 7) << 5;
        const int s   = (dt - (TK_ - 1) / 2) * V_;
        const uint32_t base = sb + (uint32_t)(it & 1) * STAGE;
        #pragma unroll
        for (int i = 0; i < 2; ++i) {
            const int c   = tid * 2 + i;     // 0..511
            const int row = c >> 2;
            const int ch  = c & 3;
            // A: weights
            const __half* asrc = wt2_buf + (size_t)dt * (C_ * C_) +
                                 (size_t)(co0 + row) * C_ + cic + ch * 8;
            cpa16(base + row * ROW_B + ch * 16, asrc, 16);
            // B: shifted g rows with zero-fill at boundaries
            const int jp = j0 + row + s;
            const bool v = (jp >= 0) && (jp < J_);
            const __half* bsrc = gtn + (size_t)(v ? jp : 0) * C_ + cic + ch * 8;
            cpa16(base + A_BYTES + row * ROW_B + ch * 16, bsrc, v ? 16 : 0);
        }
        cpa_commit();
    };

    load_stage(0);

    for (int it = 0; it < NUM_IT; ++it) {
        if (it + 1 < NUM_IT) {
            load_stage(it + 1);
            cpa_wait<1>();
        } else {
            cpa_wait<0>();
        }
        __syncthreads();

        const uint32_t base = sb + (uint32_t)(it & 1) * STAGE;
        #pragma unroll
        for (int ks = 0; ks < 2; ++ks) {
            uint32_t aa[2][4], bb[4][4];
            #pragma unroll
            for (int mi = 0; mi < 2; ++mi)
                ldsm4(aa[mi], base + offA[mi] + ks * 32);
            #pragma unroll
            for (int nb = 0; nb < 4; ++nb)
                ldsm4(bb[nb], base + offB[nb] + ks * 32);
            #pragma unroll
            for (int mi = 0; mi < 2; ++mi)
                #pragma unroll
                for (int nf = 0; nf < 8; ++nf) {
                    const int nb = nf >> 1;
                    if (nf & 1)
                        mma16816(acc[mi][nf], aa[mi], bb[nb][2], bb[nb][3]);
                    else
                        mma16816(acc[mi][nf], aa[mi], bb[nb][0], bb[nb][1]);
                }
        }
        __syncthreads();
    }

    // ---- epilogue: BN2 + ReLU + residual ----
    #pragma unroll
    for (int mi = 0; mi < 2; ++mi) {
        #pragma unroll
        for (int hh = 0; hh < 2; ++hh) {
            const int co = co0 + cw + mi * 16 + (lane >> 2) + hh * 8;
            const float scl = g2[co] * rsqrtf(v2[co] + BN_EPS);
            const float shf = b2[co] - m2[co] * scl + tcb[co] * scl;
            const float* xr = x   + (size_t)(n * C_ + co) * J_;
            float* orow     = out + (size_t)(n * C_ + co) * J_;
            #pragma unroll
            for (int nf = 0; nf < 8; ++nf) {
                const int jj = j0 + jw + nf * 8 + (lane & 3) * 2;
                if (jj < J_) {
                    float v0 = fmaf(acc[mi][nf][hh * 2 + 0], scl, shf);
                    float v1 = fmaf(acc[mi][nf][hh * 2 + 1], scl, shf);
                    v0 = v0 > 0.f ? v0 : 0.f;
                    v1 = v1 > 0.f ? v1 : 0.f;
                    float2 xv = *(const float2*)(xr + jj);
                    float2 o;
                    o.x = v0 + xv.x;
                    o.y = v1 + xv.y;
                    *(float2*)(orow + jj) = o;
                }
            }
        }
    }
}

// ---------------------------------------------------------------------------
extern "C" void kernel_launch(void* const* d_in, const int* in_sizes, int n_in,
                              void* d_out, int out_size)
{
    const float* x   = (const float*)d_in[0];
    const float* A   = (const float*)d_in[1];
    // d_in[2] = att_A (unused by this block)
    const float* Mm  = (const float*)d_in[3];
    const float* W   = (const float*)d_in[4];
    const float* cb  = (const float*)d_in[5];
    const float* g1  = (const float*)d_in[6];
    const float* b1  = (const float*)d_in[7];
    const float* m1  = (const float*)d_in[8];
    const float* v1  = (const float*)d_in[9];
    const float* tw  = (const float*)d_in[10];
    const float* tcb = (const float*)d_in[11];
    const float* g2  = (const float*)d_in[12];
    const float* b2  = (const float*)d_in[13];
    const float* m2  = (const float*)d_in[14];
    const float* v2  = (const float*)d_in[15];
    float* out = (float*)d_out;

    const int smem1 = (C_ * V_ + K_ * V_ * V_ + 32 * 769) * (int)sizeof(float);
    cudaFuncSetAttribute(sgc_kernel, cudaFuncAttributeMaxDynamicSharedMemorySize, smem1);

    // K0: weight transform -> fp16 [dt][co][ci]
    wt2_kernel<<<(TK_ * C_ * C_ + 255) / 256, 256>>>(tw);

    // K1: S_GC + BN1 + ReLU -> g_t (transposed fp16)
    dim3 grid1(T_, N_);
    sgc_kernel<<<grid1, 256, smem1>>>(x, A, Mm, W, cb, g1, b1, m1, v1);

    // K2: temporal conv via mma.sync fp16 + BN2 + ReLU + residual
    dim3 grid2((J_ + 127) / 128, C_ / 128, N_);
    tconv_mma_kernel<<<grid2, 256>>>(x, tcb, g2, b2, m2, v2, out);
}

// round 4
// speedup vs baseline: 8.8521x; 4.9640x over previous
#include <cuda_runtime.h>
#include <cuda_fp16.h>
#include <cstdint>

#define N_ 16
#define C_ 256
#define T_ 300
#define V_ 25
#define K_ 3
#define TK_ 9
#define J_ 7500
#define KD1 768            // GEMM1 K-dim (k,ci)
#define BN_EPS 1e-5f

// static device scratch
__device__ __align__(256) __half xa_buf[(size_t)N_ * J_ * KD1];   // 184 MB
__device__ __align__(256) __half gt_buf[(size_t)N_ * J_ * C_];    // 61.4 MB
__device__ __align__(256) __half wt2_buf[TK_ * C_ * C_];          // [dt][co][ci]
__device__ __align__(256) __half wa_buf[C_ * KD1];                // [co][(k,ci)]
__device__ float bcw_buf[C_ * V_];                                // bias*sum(AM)

// ---------------------------------------------------------------------------
// PTX helpers
// ---------------------------------------------------------------------------
__device__ __forceinline__ uint32_t smem_u32(const void* p) {
    uint32_t a;
    asm("{ .reg .u64 t; cvta.to.shared.u64 t, %1; cvt.u32.u64 %0, t; }" : "=r"(a) : "l"(p));
    return a;
}
__device__ __forceinline__ void ldsm4(uint32_t* r, uint32_t addr) {
    asm volatile("ldmatrix.sync.aligned.m8n8.x4.shared.b16 {%0,%1,%2,%3}, [%4];"
                 : "=r"(r[0]), "=r"(r[1]), "=r"(r[2]), "=r"(r[3]) : "r"(addr));
}
__device__ __forceinline__ void mma16816(float* c, const uint32_t* a,
                                         uint32_t b0, uint32_t b1) {
    asm volatile(
        "mma.sync.aligned.m16n8k16.row.col.f32.f16.f16.f32 "
        "{%0,%1,%2,%3}, {%4,%5,%6,%7}, {%8,%9}, {%0,%1,%2,%3};"
        : "+f"(c[0]), "+f"(c[1]), "+f"(c[2]), "+f"(c[3])
        : "r"(a[0]), "r"(a[1]), "r"(a[2]), "r"(a[3]), "r"(b0), "r"(b1));
}
__device__ __forceinline__ void cpa16(uint32_t dst, const void* src, int srcsize) {
    asm volatile("cp.async.cg.shared.global [%0], [%1], 16, %2;"
                 :: "r"(dst), "l"(src), "r"(srcsize));
}
__device__ __forceinline__ void cpa_commit() {
    asm volatile("cp.async.commit_group;" ::: "memory");
}
template <int NN>
__device__ __forceinline__ void cpa_wait() {
    asm volatile("cp.async.wait_group %0;" :: "n"(NN) : "memory");
}

// ---------------------------------------------------------------------------
// prep kernels
// ---------------------------------------------------------------------------
__global__ void wt2_kernel(const float* __restrict__ tw) {
    int i = blockIdx.x * 256 + threadIdx.x;
    if (i < TK_ * C_ * C_) {
        int dt = i / (C_ * C_);
        int r  = i - dt * C_ * C_;
        int co = r >> 8;
        int ci = r & 255;
        wt2_buf[i] = __float2half_rn(tw[(co * C_ + ci) * TK_ + dt]);
    }
}

__global__ void wa_kernel(const float* __restrict__ cw) {
    int i = blockIdx.x * 256 + threadIdx.x;
    if (i < C_ * KD1) {
        int co = i / KD1;
        int kk = i - co * KD1;
        int k  = kk >> 8;
        int ci = kk & 255;
        wa_buf[i] = __float2half_rn(cw[(k * C_ + co) * C_ + ci]);
    }
}

__global__ void bcw_kernel(const float* __restrict__ A, const float* __restrict__ Mm,
                           const float* __restrict__ bias) {
    __shared__ float S[K_ * V_];
    int tid = threadIdx.x;
    if (tid < K_ * V_) {
        int k = tid / V_;
        int w = tid - k * V_;
        float s = 0.f;
        for (int v = 0; v < V_; ++v) {
            int idx = (k * V_ + v) * V_ + w;
            s += A[idx] * Mm[idx];
        }
        S[tid] = s;
    }
    __syncthreads();
    int c = tid;   // 256 threads
    for (int w = 0; w < V_; ++w) {
        float s = 0.f;
        #pragma unroll
        for (int k = 0; k < K_; ++k)
            s += bias[k * C_ + c] * S[k * V_ + w];
        bcw_buf[c * V_ + w] = s;
    }
}

// ---------------------------------------------------------------------------
// xa kernel: xa[n][j=(t,w)][(k,ci)] = sum_v x[n,ci,t,v] * (A*M)[k,v,w]   (fp16)
// one block per (t, n); thread = ci
// ---------------------------------------------------------------------------
__global__ void __launch_bounds__(256) xa_kernel(
    const float* __restrict__ x, const float* __restrict__ A,
    const float* __restrict__ Mm)
{
    __shared__ float xs[C_ * V_];
    __shared__ float AMt[K_ * V_ * 28];   // [k][w][v-padded]

    const int t = blockIdx.x;
    const int n = blockIdx.y;
    const int tid = threadIdx.x;

    for (int i = tid; i < C_ * V_; i += 256) {
        int ci = i / V_;
        int v  = i - ci * V_;
        xs[i] = x[((size_t)(n * C_ + ci) * T_ + t) * V_ + v];
    }
    for (int i = tid; i < K_ * V_ * V_; i += 256) {
        int k = i / (V_ * V_);
        int r = i - k * (V_ * V_);
        int v = r / V_;
        int w = r - v * V_;
        AMt[(k * V_ + w) * 28 + v] = A[i] * Mm[i];
    }
    __syncthreads();

    float xv[V_];
    #pragma unroll
    for (int v = 0; v < V_; ++v) xv[v] = xs[tid * V_ + v];

    __half* outb = xa_buf + ((size_t)n * J_ + t * V_) * KD1;
    #pragma unroll
    for (int k = 0; k < K_; ++k) {
        for (int w = 0; w < V_; ++w) {
            const float* amr = AMt + (k * V_ + w) * 28;
            float s = 0.f;
            #pragma unroll
            for (int q = 0; q < 6; ++q) {
                float4 a4 = *(const float4*)(amr + q * 4);
                s = fmaf(xv[q * 4 + 0], a4.x, s);
                s = fmaf(xv[q * 4 + 1], a4.y, s);
                s = fmaf(xv[q * 4 + 2], a4.z, s);
                s = fmaf(xv[q * 4 + 3], a4.w, s);
            }
            s = fmaf(xv[24], amr[24], s);
            outb[(size_t)w * KD1 + k * C_ + tid] = __float2half_rn(s);
        }
    }
}

// ---------------------------------------------------------------------------
// shared GEMM plumbing: tile 128(co) x 128(j), k-chunk 64, 3-stage cp.async
// ---------------------------------------------------------------------------
#define G_STAGE 32768
#define G_SMEM  98304

// ---------------------------------------------------------------------------
// GEMM1: sgc = Wa @ xa  -> BN1+ReLU+bcw -> gt[n][j][c] fp16 (smem transpose)
// ---------------------------------------------------------------------------
#define IT1 12

__global__ void __launch_bounds__(256, 2) gemm1_kernel(
    const float* __restrict__ g1, const float* __restrict__ b1,
    const float* __restrict__ m1, const float* __restrict__ v1)
{
    extern __shared__ char smraw[];
    const uint32_t sb = smem_u32(smraw);
    const int tid  = threadIdx.x;
    const int wid  = tid >> 5;
    const int lane = tid & 31;
    const int j0   = blockIdx.x * 128;
    const int co0  = blockIdx.y * 128;
    const int n    = blockIdx.z;
    const int cw = (wid & 3) * 32;
    const int jw = (wid >> 2) * 64;

    const __half* xan = xa_buf + (size_t)n * J_ * KD1;

    float acc[2][8][4];
    #pragma unroll
    for (int mi = 0; mi < 2; ++mi)
        #pragma unroll
        for (int nf = 0; nf < 8; ++nf)
            #pragma unroll
            for (int q = 0; q < 4; ++q) acc[mi][nf][q] = 0.f;

    auto load_stage = [&](int it, int slot) {
        const uint32_t base = sb + (uint32_t)slot * G_STAGE;
        const int kb = it * 64;
        #pragma unroll
        for (int q = 0; q < 4; ++q) {
            const int c   = tid + q * 256;
            const int row = c >> 3;
            const int ch  = c & 7;
            const uint32_t sw = (uint32_t)((ch ^ (row & 7)) << 4);
            const __half* as = wa_buf + (size_t)(co0 + row) * KD1 + kb + ch * 8;
            cpa16(base + row * 128 + sw, as, 16);
            const int jp = j0 + row;
            const bool v = jp < J_;
            const __half* bs = xan + (size_t)(v ? jp : 0) * KD1 + kb + ch * 8;
            cpa16(base + 16384 + row * 128 + sw, bs, v ? 16 : 0);
        }
        cpa_commit();
    };

    load_stage(0, 0);
    load_stage(1, 1);

    const int rs  = lane & 7;
    const int hiA = lane >> 4;
    const int hiB = (lane >> 3) & 1;
    uint32_t rowA[2], rowB[4];
    #pragma unroll
    for (int mi = 0; mi < 2; ++mi)
        rowA[mi] = (uint32_t)((cw + mi * 16 + (lane & 15)) * 128);
    #pragma unroll
    for (int nb = 0; nb < 4; ++nb)
        rowB[nb] = (uint32_t)((jw + nb * 16 + (lane & 7) + (((lane >> 4) & 1) << 3)) * 128 + 16384);

    int wslot = 2, cslot = 0;
    for (int it = 0; it < IT1; ++it) {
        if (it < IT1 - 1) cpa_wait<1>(); else cpa_wait<0>();
        __syncthreads();
        if (it + 2 < IT1) {
            load_stage(it + 2, wslot);
            wslot = (wslot == 2) ? 0 : wslot + 1;
        }
        const uint32_t base = sb + (uint32_t)cslot * G_STAGE;
        cslot = (cslot == 2) ? 0 : cslot + 1;
        #pragma unroll
        for (int ks = 0; ks < 4; ++ks) {
            uint32_t aa[2][4], bb[4][4];
            #pragma unroll
            for (int mi = 0; mi < 2; ++mi)
                ldsm4(aa[mi], base + rowA[mi] + (uint32_t)((((ks * 2 + hiA) ^ rs)) << 4));
            #pragma unroll
            for (int nb = 0; nb < 4; ++nb)
                ldsm4(bb[nb], base + rowB[nb] + (uint32_t)((((ks * 2 + hiB) ^ rs)) << 4));
            #pragma unroll
            for (int mi = 0; mi < 2; ++mi)
                #pragma unroll
                for (int nf = 0; nf < 8; ++nf) {
                    const int nb = nf >> 1;
                    if (nf & 1) mma16816(acc[mi][nf], aa[mi], bb[nb][2], bb[nb][3]);
                    else        mma16816(acc[mi][nf], aa[mi], bb[nb][0], bb[nb][1]);
                }
        }
    }
    __syncthreads();

    // epilogue: bcw + BN1 + ReLU -> smem transpose tile ts[j][co] -> gt[j][c]
    __half* ts = (__half*)smraw;   // [128][136]
    #pragma unroll
    for (int mi = 0; mi < 2; ++mi) {
        #pragma unroll
        for (int hh = 0; hh < 2; ++hh) {
            const int col = cw + mi * 16 + (lane >> 2) + hh * 8;
            const int cog = co0 + col;
            const float scl = g1[cog] * rsqrtf(v1[cog] + BN_EPS);
            const float shf = b1[cog] - m1[cog] * scl;
            const float* bcr = bcw_buf + cog * V_;
            #pragma unroll
            for (int nf = 0; nf < 8; ++nf) {
                const int jl = jw + nf * 8 + (lane & 3) * 2;
                const int jg = j0 + jl;
                const int w0 = jg % 25;
                const int w1 = (w0 == 24) ? 0 : w0 + 1;
                float r0 = acc[mi][nf][hh * 2 + 0] + bcr[w0];
                float r1 = acc[mi][nf][hh * 2 + 1] + bcr[w1];
                r0 = fmaf(r0, scl, shf);
                r1 = fmaf(r1, scl, shf);
                r0 = r0 > 0.f ? r0 : 0.f;
                r1 = r1 > 0.f ? r1 : 0.f;
                ts[jl * 136 + col]       = __float2half_rn(r0);
                ts[(jl + 1) * 136 + col] = __float2half_rn(r1);
            }
        }
    }
    __syncthreads();

    __half* gout = gt_buf + (size_t)n * J_ * C_;
    #pragma unroll
    for (int p = 0; p < 8; ++p) {
        const int idx = p * 256 + tid;
        const int cc = idx & 15;
        const int j  = idx >> 4;
        const int jg = j0 + j;
        if (jg < J_) {
            uint4 vv = *(const uint4*)(ts + j * 136 + cc * 8);
            *(uint4*)(gout + (size_t)jg * C_ + co0 + cc * 8) = vv;
        }
    }
}

// ---------------------------------------------------------------------------
// GEMM2: temporal conv (K = 9*256) + BN2 + ReLU + residual -> out
// ---------------------------------------------------------------------------
#define IT2 36

__global__ void __launch_bounds__(256, 2) gemm2_kernel(
    const float* __restrict__ x, const float* __restrict__ tcb,
    const float* __restrict__ g2, const float* __restrict__ b2,
    const float* __restrict__ m2, const float* __restrict__ v2,
    float* __restrict__ out)
{
    extern __shared__ char smraw2[];
    const uint32_t sb = smem_u32(smraw2);
    const int tid  = threadIdx.x;
    const int wid  = tid >> 5;
    const int lane = tid & 31;
    const int j0   = blockIdx.x * 128;
    const int co0  = blockIdx.y * 128;
    const int n    = blockIdx.z;
    const int cw = (wid & 3) * 32;
    const int jw = (wid >> 2) * 64;

    const __half* gtn = gt_buf + (size_t)n * J_ * C_;

    float acc[2][8][4];
    #pragma unroll
    for (int mi = 0; mi < 2; ++mi)
        #pragma unroll
        for (int nf = 0; nf < 8; ++nf)
            #pragma unroll
            for (int q = 0; q < 4; ++q) acc[mi][nf][q] = 0.f;

    auto load_stage = [&](int it, int slot) {
        const uint32_t base = sb + (uint32_t)slot * G_STAGE;
        const int dt  = it >> 2;
        const int cic = (it & 3) << 6;
        const int s   = (dt - (TK_ - 1) / 2) * V_;
        #pragma unroll
        for (int q = 0; q < 4; ++q) {
            const int c   = tid + q * 256;
            const int row = c >> 3;
            const int ch  = c & 7;
            const uint32_t sw = (uint32_t)((ch ^ (row & 7)) << 4);
            const __half* as = wt2_buf + (size_t)dt * (C_ * C_) +
                               (size_t)(co0 + row) * C_ + cic + ch * 8;
            cpa16(base + row * 128 + sw, as, 16);
            const int jp = j0 + row + s;
            const bool v = (jp >= 0) && (jp < J_);
            const __half* bs = gtn + (size_t)(v ? jp : 0) * C_ + cic + ch * 8;
            cpa16(base + 16384 + row * 128 + sw, bs, v ? 16 : 0);
        }
        cpa_commit();
    };

    load_stage(0, 0);
    load_stage(1, 1);

    const int rs  = lane & 7;
    const int hiA = lane >> 4;
    const int hiB = (lane >> 3) & 1;
    uint32_t rowA[2], rowB[4];
    #pragma unroll
    for (int mi = 0; mi < 2; ++mi)
        rowA[mi] = (uint32_t)((cw + mi * 16 + (lane & 15)) * 128);
    #pragma unroll
    for (int nb = 0; nb < 4; ++nb)
        rowB[nb] = (uint32_t)((jw + nb * 16 + (lane & 7) + (((lane >> 4) & 1) << 3)) * 128 + 16384);

    int wslot = 2, cslot = 0;
    for (int it = 0; it < IT2; ++it) {
        if (it < IT2 - 1) cpa_wait<1>(); else cpa_wait<0>();
        __syncthreads();
        if (it + 2 < IT2) {
            load_stage(it + 2, wslot);
            wslot = (wslot == 2) ? 0 : wslot + 1;
        }
        const uint32_t base = sb + (uint32_t)cslot * G_STAGE;
        cslot = (cslot == 2) ? 0 : cslot + 1;
        #pragma unroll
        for (int ks = 0; ks < 4; ++ks) {
            uint32_t aa[2][4], bb[4][4];
            #pragma unroll
            for (int mi = 0; mi < 2; ++mi)
                ldsm4(aa[mi], base + rowA[mi] + (uint32_t)((((ks * 2 + hiA) ^ rs)) << 4));
            #pragma unroll
            for (int nb = 0; nb < 4; ++nb)
                ldsm4(bb[nb], base + rowB[nb] + (uint32_t)((((ks * 2 + hiB) ^ rs)) << 4));
            #pragma unroll
            for (int mi = 0; mi < 2; ++mi)
                #pragma unroll
                for (int nf = 0; nf < 8; ++nf) {
                    const int nb = nf >> 1;
                    if (nf & 1) mma16816(acc[mi][nf], aa[mi], bb[nb][2], bb[nb][3]);
                    else        mma16816(acc[mi][nf], aa[mi], bb[nb][0], bb[nb][1]);
                }
        }
    }

    // epilogue: BN2 + ReLU + residual
    #pragma unroll
    for (int mi = 0; mi < 2; ++mi) {
        #pragma unroll
        for (int hh = 0; hh < 2; ++hh) {
            const int co = co0 + cw + mi * 16 + (lane >> 2) + hh * 8;
            const float scl = g2[co] * rsqrtf(v2[co] + BN_EPS);
            const float shf = b2[co] - m2[co] * scl + tcb[co] * scl;
            const float* xr = x   + (size_t)(n * C_ + co) * J_;
            float* orow     = out + (size_t)(n * C_ + co) * J_;
            #pragma unroll
            for (int nf = 0; nf < 8; ++nf) {
                const int jj = j0 + jw + nf * 8 + (lane & 3) * 2;
                if (jj < J_) {
                    float v0 = fmaf(acc[mi][nf][hh * 2 + 0], scl, shf);
                    float v1 = fmaf(acc[mi][nf][hh * 2 + 1], scl, shf);
                    v0 = v0 > 0.f ? v0 : 0.f;
                    v1 = v1 > 0.f ? v1 : 0.f;
                    float2 xv = *(const float2*)(xr + jj);
                    float2 o;
                    o.x = v0 + xv.x;
                    o.y = v1 + xv.y;
                    *(float2*)(orow + jj) = o;
                }
            }
        }
    }
}

// ---------------------------------------------------------------------------
extern "C" void kernel_launch(void* const* d_in, const int* in_sizes, int n_in,
                              void* d_out, int out_size)
{
    const float* x   = (const float*)d_in[0];
    const float* A   = (const float*)d_in[1];
    // d_in[2] = att_A (unused)
    const float* Mm  = (const float*)d_in[3];
    const float* W   = (const float*)d_in[4];
    const float* cb  = (const float*)d_in[5];
    const float* g1  = (const float*)d_in[6];
    const float* b1  = (const float*)d_in[7];
    const float* m1  = (const float*)d_in[8];
    const float* v1  = (const float*)d_in[9];
    const float* tw  = (const float*)d_in[10];
    const float* tcb = (const float*)d_in[11];
    const float* g2  = (const float*)d_in[12];
    const float* b2  = (const float*)d_in[13];
    const float* m2  = (const float*)d_in[14];
    const float* v2  = (const float*)d_in[15];
    float* out = (float*)d_out;

    cudaFuncSetAttribute(gemm1_kernel, cudaFuncAttributeMaxDynamicSharedMemorySize, G_SMEM);
    cudaFuncSetAttribute(gemm2_kernel, cudaFuncAttributeMaxDynamicSharedMemorySize, G_SMEM);

    // prep
    wt2_kernel<<<(TK_ * C_ * C_ + 255) / 256, 256>>>(tw);
    wa_kernel<<<(C_ * KD1 + 255) / 256, 256>>>(W);
    bcw_kernel<<<1, 256>>>(A, Mm, cb);

    // xa: graph-contracted input
    dim3 gxa(T_, N_);
    xa_kernel<<<gxa, 256>>>(x, A, Mm);

    // GEMM1: S_GC + BN1 + ReLU -> gt
    dim3 gg1((J_ + 127) / 128, C_ / 128, N_);
    gemm1_kernel<<<gg1, 256, G_SMEM>>>(g1, b1, m1, v1);

    // GEMM2: temporal conv + BN2 + ReLU + residual
    dim3 gg2((J_ + 127) / 128, C_ / 128, N_);
    gemm2_kernel<<<gg2, 256, G_SMEM>>>(x, tcb, g2, b2, m2, v2, out);
}